// round 3
// baseline (speedup 1.0000x reference)
#include <cuda_runtime.h>
#include <math.h>

#define Bq 8
#define Cc 192
#define HH 128
#define WW 128
#define HWsz (HH*WW)      // 16384
#define C3 (3*Cc)         // 576
#define NHEADS 4
#define Dh 48             // C / heads

// ---- scratch (device globals: no cudaMalloc allowed) ----
__device__ float g_qkv[(long)Bq*C3*HWsz];    // after 1x1 conv
__device__ float g_qkvdw[(long)Bq*C3*HWsz];  // after depthwise 3x3
__device__ float g_norms[Bq*2*Cc];           // sum of squares for q,k rows
__device__ float g_gram[Bq*NHEADS*Dh*Dh];    // raw gram -> attn (in place)
__device__ float g_M[Bq*Cc*Cc];              // proj_w folded with attn

// ---------------- zero init ----------------
__global__ void zero_kernel(float* p0, int n0, float* p1, int n1) {
    int i = blockIdx.x * blockDim.x + threadIdx.x;
    if (i < n0) p0[i] = 0.f;
    if (i < n1) p1[i] = 0.f;
}

// ---------------- helpers ----------------
__device__ __forceinline__ unsigned f2tf32(float x) {
    unsigned r;
    asm("cvt.rna.tf32.f32 %0, %1;" : "=r"(r) : "f"(x));
    return r;
}
__device__ __forceinline__ unsigned saddr(const void* p) {
    return (unsigned)__cvta_generic_to_shared(p);
}
__device__ __forceinline__ void cp16(unsigned dst, const void* src, int sz) {
    asm volatile("cp.async.ca.shared.global [%0], [%1], 16, %2;"
                 :: "r"(dst), "l"(src), "r"(sz));
}
__device__ __forceinline__ void cp_commit() {
    asm volatile("cp.async.commit_group;");
}
__device__ __forceinline__ void cp_wait_all() {
    asm volatile("cp.async.wait_group 0;");
}
// D += A*B, m16n8k8 tf32. a: {(g,t),(g+8,t),(g,t+4),(g+8,t+4)}
// c: {(g, 2t), (g, 2t+1), (g+8, 2t), (g+8, 2t+1)}
__device__ __forceinline__ void mma_tf32(float* c, const unsigned* a,
                                         unsigned b0, unsigned b1) {
    asm volatile(
        "mma.sync.aligned.m16n8k8.row.col.f32.tf32.tf32.f32 "
        "{%0,%1,%2,%3}, {%4,%5,%6,%7}, {%8,%9}, {%0,%1,%2,%3};"
        : "+f"(c[0]), "+f"(c[1]), "+f"(c[2]), "+f"(c[3])
        : "r"(a[0]), "r"(a[1]), "r"(a[2]), "r"(a[3]), "r"(b0), "r"(b1));
}

// ---------------- tf32 GEMM, cp.async double-buffered ----------------
// C[m,n] = sum_k A[m,k]*B[k,n] + bias[m], batched by blockIdx.z with strides.
// BM=128 BN=128 BK=16, 256 threads (8 warps, 4Mx2N), warp tile 32x64.
#define GBM 128
#define GBN 128
#define GBK 16
__global__ void __launch_bounds__(256)
tf32_gemm_bias_kernel(const float* __restrict__ A, long sA,
                      const float* __restrict__ B, long sB,
                      float* __restrict__ C, long sC,
                      const float* __restrict__ bias,
                      int M, int N, int K)
{
    __shared__ float As[2][GBM][20];    // [m][k], pad 4 (stride 20: conflict-free)
    __shared__ float Bs[2][GBK][136];   // [k][n], pad 8 (stride 136: conflict-free)

    const int bz = blockIdx.z;
    const float* Ab = A + (long)bz * sA;
    const float* Bb = B + (long)bz * sB;
    float* Cb = C + (long)bz * sC;

    const int m0 = blockIdx.y * GBM;
    const int n0 = blockIdx.x * GBN;
    const int tid  = threadIdx.x;
    const int wid  = tid >> 5;
    const int lane = tid & 31;
    const int gid  = lane >> 2;
    const int tig  = lane & 3;
    const int wm = (wid & 3) * 32;
    const int wn = (wid >> 2) * 64;

    float acc[2][8][4];
    #pragma unroll
    for (int i = 0; i < 2; i++)
        #pragma unroll
        for (int j = 0; j < 8; j++)
            #pragma unroll
            for (int q = 0; q < 4; q++) acc[i][j][q] = 0.f;

    const int NT = K / GBK;

    // tile loader: A rows guarded (zero-fill OOB), B unguarded (K,N exact)
    auto load_tile = [&](int it, int s) {
        const int k0 = it * GBK;
        #pragma unroll
        for (int f = tid; f < 512; f += 256) {
            int m  = f >> 2;
            int q4 = (f & 3) << 2;
            bool p = (m0 + m) < M;
            const float* src = p ? (Ab + (long)(m0+m)*K + k0 + q4) : Ab;
            cp16(saddr(&As[s][m][q4]), src, p ? 16 : 0);
        }
        #pragma unroll
        for (int f = tid; f < 512; f += 256) {
            int k  = f >> 5;
            int c4 = (f & 31) << 2;
            cp16(saddr(&Bs[s][k][c4]), Bb + (long)(k0+k)*N + n0 + c4, 16);
        }
        cp_commit();
    };

    load_tile(0, 0);

    for (int it = 0; it < NT; it++) {
        cp_wait_all();
        __syncthreads();
        if (it + 1 < NT) load_tile(it + 1, (it + 1) & 1);
        const int s = it & 1;

        #pragma unroll
        for (int ks = 0; ks < GBK; ks += 8) {
            unsigned a[2][4];
            #pragma unroll
            for (int mi = 0; mi < 2; mi++) {
                int mr = wm + mi*16;
                a[mi][0] = f2tf32(As[s][mr + gid    ][ks + tig    ]);
                a[mi][1] = f2tf32(As[s][mr + gid + 8][ks + tig    ]);
                a[mi][2] = f2tf32(As[s][mr + gid    ][ks + tig + 4]);
                a[mi][3] = f2tf32(As[s][mr + gid + 8][ks + tig + 4]);
            }
            #pragma unroll
            for (int ni = 0; ni < 8; ni++) {
                int nb = wn + ni*8;
                unsigned b0 = f2tf32(Bs[s][ks + tig    ][nb + gid]);
                unsigned b1 = f2tf32(Bs[s][ks + tig + 4][nb + gid]);
                #pragma unroll
                for (int mi = 0; mi < 2; mi++)
                    mma_tf32(acc[mi][ni], a[mi], b0, b1);
            }
        }
        __syncthreads();
    }

    #pragma unroll
    for (int mi = 0; mi < 2; mi++) {
        int r0 = m0 + wm + mi*16 + gid;
        int r1 = r0 + 8;
        float bv0 = (r0 < M && bias) ? bias[r0] : 0.f;
        float bv1 = (r1 < M && bias) ? bias[r1] : 0.f;
        #pragma unroll
        for (int ni = 0; ni < 8; ni++) {
            int col = n0 + wn + ni*8 + tig*2;
            if (r0 < M) {
                float2 v; v.x = acc[mi][ni][0] + bv0; v.y = acc[mi][ni][1] + bv0;
                *(float2*)(Cb + (long)r0*N + col) = v;
            }
            if (r1 < M) {
                float2 v; v.x = acc[mi][ni][2] + bv1; v.y = acc[mi][ni][3] + bv1;
                *(float2*)(Cb + (long)r1*N + col) = v;
            }
        }
    }
}

// ---------------- depthwise 3x3, 4 pixels/thread (no norms) ----------------
__global__ void __launch_bounds__(256)
dwconv_kernel(const float* __restrict__ in,
              const float* __restrict__ w,
              const float* __restrict__ bias,
              float* __restrict__ out)
{
    const int bc = blockIdx.x;            // b*C3 + ch
    const int ch = bc % C3;
    const int tid = threadIdx.x;
    const int t = blockIdx.y * 256 + tid;
    const int y  = t >> 5;
    const int x  = (t & 31) << 2;

    const float* ip = in + (long)bc * HWsz;
    float wv[9];
    #pragma unroll
    for (int i = 0; i < 9; i++) wv[i] = w[ch*9 + i];

    float row[3][6];
    #pragma unroll
    for (int r = 0; r < 3; r++) {
        int yy = y + r - 1;
        if (yy >= 0 && yy < HH) {
            const float* rp = ip + yy*WW;
            float4 v = *(const float4*)(rp + x);
            row[r][1] = v.x; row[r][2] = v.y; row[r][3] = v.z; row[r][4] = v.w;
            row[r][0] = (x > 0)       ? rp[x-1] : 0.f;
            row[r][5] = (x + 4 < WW)  ? rp[x+4] : 0.f;
        } else {
            #pragma unroll
            for (int c = 0; c < 6; c++) row[r][c] = 0.f;
        }
    }

    const float bv = bias[ch];
    float4 ov;
    float* o = (float*)&ov;
    #pragma unroll
    for (int j = 0; j < 4; j++) {
        float acc = bv;
        #pragma unroll
        for (int r = 0; r < 3; r++) {
            acc = fmaf(wv[r*3+0], row[r][j+0], acc);
            acc = fmaf(wv[r*3+1], row[r][j+1], acc);
            acc = fmaf(wv[r*3+2], row[r][j+2], acc);
        }
        o[j] = acc;
    }
    *(float4*)(out + (long)bc * HWsz + y*WW + x) = ov;
}

// ---------------- gram via tf32 mma with hi/lo compensation + norms ----------
// D[d,e] = sum_p q[d,p]*k[e,p]  (48x48 per (b,h)), split over pixels.
// Per block: 128 threads = 4 warps; each warp owns an 8-pixel k-slice of a
// 32-pixel smem tile. Tiles stored [pixel][d] as tf32 hi/lo.
// D ~= Qh*Kh + Qh*Kl + Ql*Kh  (error ~2^-21, fp32-class).
#define GSPLIT 16
#define GCHUNK (HWsz/GSPLIT)   // 1024
#define GTP 32                 // pixels per smem tile
#define GST 52                 // smem stride (52%32=20 -> conflict-free frags)
__global__ void __launch_bounds__(128)
gram_mma_kernel(const float* __restrict__ qk,
                float* __restrict__ gram,
                float* __restrict__ norms)
{
    const int bh = blockIdx.x;
    const int split = blockIdx.y;
    const int b = bh >> 2, h = bh & 3;

    const float* qp = qk + ((long)b*C3 + h*Dh) * HWsz;
    const float* kp = qk + ((long)b*C3 + Cc + h*Dh) * HWsz;

    __shared__ unsigned tiles[4][GTP][GST];  // Qh, Ql, Kh, Kl
    __shared__ float snq[Dh], snk[Dh];

    unsigned (*Qh)[GST] = tiles[0];
    unsigned (*Ql)[GST] = tiles[1];
    unsigned (*Kh)[GST] = tiles[2];
    unsigned (*Kl)[GST] = tiles[3];

    const int tid  = threadIdx.x;
    const int wid  = tid >> 5;
    const int lane = tid & 31;
    const int gid  = lane >> 2;
    const int tig  = lane & 3;
    const int kw   = wid * 8;     // this warp's pixel slice within tile

    if (tid < Dh) { snq[tid] = 0.f; snk[tid] = 0.f; }
    __syncthreads();

    float acc[18][4];
    #pragma unroll
    for (int i = 0; i < 18; i++)
        #pragma unroll
        for (int q = 0; q < 4; q++) acc[i][q] = 0.f;

    const int nbase = split * GCHUNK;

    for (int t = 0; t < GCHUNK; t += GTP) {
        // load 48 rows x 32 px for q and k: 384 float4 each, 128 threads -> 3 ea
        #pragma unroll
        for (int f = tid; f < Dh * (GTP/4); f += 128) {
            int r = f >> 3;            // d row
            int c = (f & 7) << 2;      // pixel
            long off = (long)r*HWsz + nbase + t + c;
            float4 v = *(const float4*)(qp + off);
            float4 u = *(const float4*)(kp + off);
            #pragma unroll
            for (int j = 0; j < 4; j++) {
                float qv = (&v.x)[j], kv = (&u.x)[j];
                unsigned qh = f2tf32(qv);
                unsigned kh = f2tf32(kv);
                Qh[c+j][r] = qh;  Ql[c+j][r] = f2tf32(qv - __uint_as_float(qh));
                Kh[c+j][r] = kh;  Kl[c+j][r] = f2tf32(kv - __uint_as_float(kh));
            }
            atomicAdd(&snq[r], v.x*v.x + v.y*v.y + v.z*v.z + v.w*v.w);
            atomicAdd(&snk[r], u.x*u.x + u.y*u.y + u.z*u.z + u.w*u.w);
        }
        __syncthreads();

        unsigned ah[3][4], al[3][4];
        #pragma unroll
        for (int mi = 0; mi < 3; mi++) {
            int mr = mi*16;
            ah[mi][0] = Qh[kw + tig    ][mr + gid    ];
            ah[mi][1] = Qh[kw + tig    ][mr + gid + 8];
            ah[mi][2] = Qh[kw + tig + 4][mr + gid    ];
            ah[mi][3] = Qh[kw + tig + 4][mr + gid + 8];
            al[mi][0] = Ql[kw + tig    ][mr + gid    ];
            al[mi][1] = Ql[kw + tig    ][mr + gid + 8];
            al[mi][2] = Ql[kw + tig + 4][mr + gid    ];
            al[mi][3] = Ql[kw + tig + 4][mr + gid + 8];
        }
        #pragma unroll
        for (int ni = 0; ni < 6; ni++) {
            int nb = ni*8;
            unsigned bh0 = Kh[kw + tig    ][nb + gid];
            unsigned bh1 = Kh[kw + tig + 4][nb + gid];
            unsigned bl0 = Kl[kw + tig    ][nb + gid];
            unsigned bl1 = Kl[kw + tig + 4][nb + gid];
            #pragma unroll
            for (int mi = 0; mi < 3; mi++) {
                float* c = acc[mi*6 + ni];
                mma_tf32(c, ah[mi], bh0, bh1);
                mma_tf32(c, ah[mi], bl0, bl1);
                mma_tf32(c, al[mi], bh0, bh1);
            }
        }
        __syncthreads();
    }

    // norms (block-partial sums)
    if (tid < Dh) {
        atomicAdd(&norms[b*2*Cc + h*Dh + tid], snq[tid]);
        atomicAdd(&norms[b*2*Cc + Cc + h*Dh + tid], snk[tid]);
    }

    // cross-warp reduce into smem (reuse tile memory), then one global add
    float (*Dred)[GST] = reinterpret_cast<float(*)[GST]>(&tiles[0][0][0]);
    for (int f = tid; f < Dh*GST; f += 128) ((float*)Dred)[f] = 0.f;
    __syncthreads();
    #pragma unroll
    for (int tn = 0; tn < 18; tn++) {
        int mr = (tn/6)*16, nb = (tn%6)*8;
        atomicAdd(&Dred[mr + gid    ][nb + tig*2    ], acc[tn][0]);
        atomicAdd(&Dred[mr + gid    ][nb + tig*2 + 1], acc[tn][1]);
        atomicAdd(&Dred[mr + gid + 8][nb + tig*2    ], acc[tn][2]);
        atomicAdd(&Dred[mr + gid + 8][nb + tig*2 + 1], acc[tn][3]);
    }
    __syncthreads();
    float* gp = gram + (long)bh * Dh * Dh;
    for (int f = tid; f < Dh*Dh; f += 128)
        atomicAdd(&gp[f], Dred[f/Dh][f%Dh]);
}

// ---------------- normalize + temperature + softmax (in place) --------
__global__ void attn_softmax_kernel(const float* __restrict__ temp,
                                    const float* __restrict__ norms,
                                    float* __restrict__ gram)
{
    int idx = blockIdx.x * blockDim.x + threadIdx.x;
    if (idx >= Bq*NHEADS*Dh) return;
    int d  = idx % Dh;
    int bh = idx / Dh;
    int h = bh % NHEADS, b = bh / NHEADS;

    float nq = fmaxf(sqrtf(norms[b*2*Cc + h*Dh + d]), 1e-12f);
    float t = temp[h];
    float* row = gram + (long)bh*Dh*Dh + d*Dh;

    float vals[Dh];
    float mx = -1e30f;
    #pragma unroll
    for (int e = 0; e < Dh; e++) {
        float nk = fmaxf(sqrtf(norms[b*2*Cc + Cc + h*Dh + e]), 1e-12f);
        float v = row[e] / (nq * nk) * t;
        vals[e] = v;
        mx = fmaxf(mx, v);
    }
    float s = 0.f;
    #pragma unroll
    for (int e = 0; e < Dh; e++) { vals[e] = expf(vals[e] - mx); s += vals[e]; }
    float inv = 1.f / s;
    #pragma unroll
    for (int e = 0; e < Dh; e++) row[e] = vals[e] * inv;
}

// ---------------- fold proj into attn ----------------
__global__ void fold_kernel(const float* __restrict__ proj_w,
                            const float* __restrict__ gram,
                            float* __restrict__ Mout)
{
    int idx = blockIdx.x * 256 + threadIdx.x;
    if (idx >= Bq*Cc*Cc) return;
    int he = idx % Cc;
    int o  = (idx / Cc) % Cc;
    int b  = idx / (Cc*Cc);
    int h = he / Dh, e = he % Dh;
    const float* attn = gram + ((long)(b*NHEADS + h)) * Dh * Dh;
    const float* pw = proj_w + (long)o*Cc + h*Dh;
    float s = 0.f;
    #pragma unroll
    for (int dl = 0; dl < Dh; dl++)
        s = fmaf(pw[dl], attn[dl*Dh + e], s);
    Mout[idx] = s;
}

// ---------------- launch ----------------
extern "C" void kernel_launch(void* const* d_in, const int* in_sizes, int n_in,
                              void* d_out, int out_size)
{
    const float* x      = (const float*)d_in[0];
    const float* qkv_w  = (const float*)d_in[1];
    const float* qkv_b  = (const float*)d_in[2];
    const float* dw_w   = (const float*)d_in[3];
    const float* dw_b   = (const float*)d_in[4];
    const float* temp   = (const float*)d_in[5];
    const float* proj_w = (const float*)d_in[6];
    const float* proj_b = (const float*)d_in[7];
    float* out = (float*)d_out;

    float *p_qkv, *p_qkvdw, *p_norms, *p_gram, *p_M;
    cudaGetSymbolAddress((void**)&p_qkv,   g_qkv);
    cudaGetSymbolAddress((void**)&p_qkvdw, g_qkvdw);
    cudaGetSymbolAddress((void**)&p_norms, g_norms);
    cudaGetSymbolAddress((void**)&p_gram,  g_gram);
    cudaGetSymbolAddress((void**)&p_M,     g_M);

    // zero accumulators
    zero_kernel<<<(Bq*NHEADS*Dh*Dh + 255)/256, 256>>>(
        p_norms, Bq*2*Cc, p_gram, Bq*NHEADS*Dh*Dh);

    // GEMM1: qkv = qkv_w @ x (per batch), tf32 mma, cp.async pipelined
    {
        dim3 grid(HWsz/GBN, (C3 + GBM - 1)/GBM, Bq);
        tf32_gemm_bias_kernel<<<grid, 256>>>(
            qkv_w, 0L,
            x, (long)Cc*HWsz,
            p_qkv, (long)C3*HWsz,
            qkv_b, C3, HWsz, Cc);
    }

    // depthwise 3x3
    {
        dim3 grid(Bq*C3, HWsz/1024);
        dwconv_kernel<<<grid, 256>>>(p_qkv, dw_w, dw_b, p_qkvdw);
    }

    // gram + norms (tf32 mma, hi/lo compensated)
    {
        dim3 grid(Bq*NHEADS, GSPLIT);
        gram_mma_kernel<<<grid, 128>>>(p_qkvdw, p_gram, p_norms);
    }

    // softmax (in place)
    attn_softmax_kernel<<<(Bq*NHEADS*Dh + 255)/256, 256>>>(temp, p_norms, p_gram);

    // fold proj_w with attn
    fold_kernel<<<(Bq*Cc*Cc + 255)/256, 256>>>(proj_w, p_gram, p_M);

    // GEMM4: out = M[b] @ v + proj_b
    {
        dim3 grid(HWsz/GBN, (Cc + GBM - 1)/GBM, Bq);
        tf32_gemm_bias_kernel<<<grid, 256>>>(
            p_M, (long)Cc*Cc,
            p_qkvdw + (long)2*Cc*HWsz, (long)C3*HWsz,
            out, (long)Cc*HWsz,
            proj_b, Cc, HWsz, Cc);
    }
}

// round 4
// speedup vs baseline: 1.1197x; 1.1197x over previous
#include <cuda_runtime.h>
#include <math.h>

#define Bq 8
#define Cc 192
#define HH 128
#define WW 128
#define HWsz (HH*WW)      // 16384
#define C3 (3*Cc)         // 576
#define NHEADS 4
#define Dh 48             // C / heads

// ---- scratch (device globals: no cudaMalloc allowed) ----
__device__ float g_qkv[(long)Bq*C3*HWsz];    // after 1x1 conv
__device__ float g_qkvdw[(long)Bq*C3*HWsz];  // after depthwise 3x3
__device__ float g_norms[Bq*2*Cc];           // sum of squares for q,k rows
__device__ float g_gram[Bq*NHEADS*Dh*Dh];    // raw gram -> attn (in place)
__device__ float g_M[Bq*Cc*Cc];              // proj_w folded with attn

// ---------------- zero init ----------------
__global__ void zero_kernel(float* p0, int n0, float* p1, int n1) {
    int i = blockIdx.x * blockDim.x + threadIdx.x;
    if (i < n0) p0[i] = 0.f;
    if (i < n1) p1[i] = 0.f;
}

// ---------------- helpers ----------------
__device__ __forceinline__ unsigned f2tf32(float x) {
    unsigned r;
    asm("cvt.rna.tf32.f32 %0, %1;" : "=r"(r) : "f"(x));
    return r;
}
__device__ __forceinline__ unsigned saddr(const void* p) {
    return (unsigned)__cvta_generic_to_shared(p);
}
__device__ __forceinline__ void cp16(unsigned dst, const void* src, int sz) {
    asm volatile("cp.async.ca.shared.global [%0], [%1], 16, %2;"
                 :: "r"(dst), "l"(src), "r"(sz));
}
__device__ __forceinline__ void cp_commit() {
    asm volatile("cp.async.commit_group;");
}
__device__ __forceinline__ void cp_wait_all() {
    asm volatile("cp.async.wait_group 0;");
}
// D += A*B, m16n8k8 tf32. a: A[m=gid][k=tig] pattern; c rows gid/gid+8, cols 2tig.
__device__ __forceinline__ void mma_tf32(float* c, const unsigned* a,
                                         unsigned b0, unsigned b1) {
    asm volatile(
        "mma.sync.aligned.m16n8k8.row.col.f32.tf32.tf32.f32 "
        "{%0,%1,%2,%3}, {%4,%5,%6,%7}, {%8,%9}, {%0,%1,%2,%3};"
        : "+f"(c[0]), "+f"(c[1]), "+f"(c[2]), "+f"(c[3])
        : "r"(a[0]), "r"(a[1]), "r"(a[2]), "r"(a[3]), "r"(b0), "r"(b1));
}

// ---------------- tf32 GEMM, cp.async double-buffered ----------------
#define GBM 128
#define GBN 128
#define GBK 16
__global__ void __launch_bounds__(256)
tf32_gemm_bias_kernel(const float* __restrict__ A, long sA,
                      const float* __restrict__ B, long sB,
                      float* __restrict__ C, long sC,
                      const float* __restrict__ bias,
                      int M, int N, int K)
{
    __shared__ float As[2][GBM][20];
    __shared__ float Bs[2][GBK][136];

    const int bz = blockIdx.z;
    const float* Ab = A + (long)bz * sA;
    const float* Bb = B + (long)bz * sB;
    float* Cb = C + (long)bz * sC;

    const int m0 = blockIdx.y * GBM;
    const int n0 = blockIdx.x * GBN;
    const int tid  = threadIdx.x;
    const int wid  = tid >> 5;
    const int lane = tid & 31;
    const int gid  = lane >> 2;
    const int tig  = lane & 3;
    const int wm = (wid & 3) * 32;
    const int wn = (wid >> 2) * 64;

    float acc[2][8][4];
    #pragma unroll
    for (int i = 0; i < 2; i++)
        #pragma unroll
        for (int j = 0; j < 8; j++)
            #pragma unroll
            for (int q = 0; q < 4; q++) acc[i][j][q] = 0.f;

    const int NT = K / GBK;

    auto load_tile = [&](int it, int s) {
        const int k0 = it * GBK;
        #pragma unroll
        for (int f = tid; f < 512; f += 256) {
            int m  = f >> 2;
            int q4 = (f & 3) << 2;
            bool p = (m0 + m) < M;
            const float* src = p ? (Ab + (long)(m0+m)*K + k0 + q4) : Ab;
            cp16(saddr(&As[s][m][q4]), src, p ? 16 : 0);
        }
        #pragma unroll
        for (int f = tid; f < 512; f += 256) {
            int k  = f >> 5;
            int c4 = (f & 31) << 2;
            cp16(saddr(&Bs[s][k][c4]), Bb + (long)(k0+k)*N + n0 + c4, 16);
        }
        cp_commit();
    };

    load_tile(0, 0);

    for (int it = 0; it < NT; it++) {
        cp_wait_all();
        __syncthreads();
        if (it + 1 < NT) load_tile(it + 1, (it + 1) & 1);
        const int s = it & 1;

        #pragma unroll
        for (int ks = 0; ks < GBK; ks += 8) {
            unsigned a[2][4];
            #pragma unroll
            for (int mi = 0; mi < 2; mi++) {
                int mr = wm + mi*16;
                a[mi][0] = f2tf32(As[s][mr + gid    ][ks + tig    ]);
                a[mi][1] = f2tf32(As[s][mr + gid + 8][ks + tig    ]);
                a[mi][2] = f2tf32(As[s][mr + gid    ][ks + tig + 4]);
                a[mi][3] = f2tf32(As[s][mr + gid + 8][ks + tig + 4]);
            }
            #pragma unroll
            for (int ni = 0; ni < 8; ni++) {
                int nb = wn + ni*8;
                unsigned b0 = f2tf32(Bs[s][ks + tig    ][nb + gid]);
                unsigned b1 = f2tf32(Bs[s][ks + tig + 4][nb + gid]);
                #pragma unroll
                for (int mi = 0; mi < 2; mi++)
                    mma_tf32(acc[mi][ni], a[mi], b0, b1);
            }
        }
        __syncthreads();
    }

    #pragma unroll
    for (int mi = 0; mi < 2; mi++) {
        int r0 = m0 + wm + mi*16 + gid;
        int r1 = r0 + 8;
        float bv0 = (r0 < M && bias) ? bias[r0] : 0.f;
        float bv1 = (r1 < M && bias) ? bias[r1] : 0.f;
        #pragma unroll
        for (int ni = 0; ni < 8; ni++) {
            int col = n0 + wn + ni*8 + tig*2;
            if (r0 < M) {
                float2 v; v.x = acc[mi][ni][0] + bv0; v.y = acc[mi][ni][1] + bv0;
                *(float2*)(Cb + (long)r0*N + col) = v;
            }
            if (r1 < M) {
                float2 v; v.x = acc[mi][ni][2] + bv1; v.y = acc[mi][ni][3] + bv1;
                *(float2*)(Cb + (long)r1*N + col) = v;
            }
        }
    }
}

// ---------------- depthwise 3x3, 4 pixels/thread ----------------
__global__ void __launch_bounds__(256)
dwconv_kernel(const float* __restrict__ in,
              const float* __restrict__ w,
              const float* __restrict__ bias,
              float* __restrict__ out)
{
    const int bc = blockIdx.x;
    const int ch = bc % C3;
    const int tid = threadIdx.x;
    const int t = blockIdx.y * 256 + tid;
    const int y  = t >> 5;
    const int x  = (t & 31) << 2;

    const float* ip = in + (long)bc * HWsz;
    float wv[9];
    #pragma unroll
    for (int i = 0; i < 9; i++) wv[i] = w[ch*9 + i];

    float row[3][6];
    #pragma unroll
    for (int r = 0; r < 3; r++) {
        int yy = y + r - 1;
        if (yy >= 0 && yy < HH) {
            const float* rp = ip + yy*WW;
            float4 v = *(const float4*)(rp + x);
            row[r][1] = v.x; row[r][2] = v.y; row[r][3] = v.z; row[r][4] = v.w;
            row[r][0] = (x > 0)       ? rp[x-1] : 0.f;
            row[r][5] = (x + 4 < WW)  ? rp[x+4] : 0.f;
        } else {
            #pragma unroll
            for (int c = 0; c < 6; c++) row[r][c] = 0.f;
        }
    }

    const float bv = bias[ch];
    float4 ov;
    float* o = (float*)&ov;
    #pragma unroll
    for (int j = 0; j < 4; j++) {
        float acc = bv;
        #pragma unroll
        for (int r = 0; r < 3; r++) {
            acc = fmaf(wv[r*3+0], row[r][j+0], acc);
            acc = fmaf(wv[r*3+1], row[r][j+1], acc);
            acc = fmaf(wv[r*3+2], row[r][j+2], acc);
        }
        o[j] = acc;
    }
    *(float4*)(out + (long)bc * HWsz + y*WW + x) = ov;
}

// ---------------- gram via tf32 mma (warp-split output, reg norms) ----------
// D[d,e] = sum_p q[d,p]*k[e,p]; hi/lo compensated: Qh*Kh + Qh*Kl + Ql*Kh.
// 192 threads = 6 warps; warp w owns output cols [w*8, w*8+8), all 48 rows
// (3 m16 tiles) -> only 12 accumulator regs per thread.
// smem layout [d][pixel], stride 36 -> conflict-free fragment loads.
#define GSPLIT 32
#define GCHUNK (HWsz/GSPLIT)   // 512
#define GTP 32                 // pixels per smem tile
#define GST 36                 // pixel stride
__global__ void __launch_bounds__(192)
gram_mma_kernel(const float* __restrict__ qk,
                float* __restrict__ gram,
                float* __restrict__ norms)
{
    const int bh = blockIdx.x;
    const int split = blockIdx.y;
    const int b = bh >> 2, h = bh & 3;

    const float* qp = qk + ((long)b*C3 + h*Dh) * HWsz;
    const float* kp = qk + ((long)b*C3 + Cc + h*Dh) * HWsz;

    __shared__ unsigned Qh[Dh][GST], Ql[Dh][GST];
    __shared__ unsigned Kh[Dh][GST], Kl[Dh][GST];

    const int tid  = threadIdx.x;
    const int wid  = tid >> 5;      // 0..5 -> n-strip
    const int lane = tid & 31;
    const int gid  = lane >> 2;
    const int tig  = lane & 3;
    const int nb   = wid * 8;

    float acc[3][4];
    #pragma unroll
    for (int i = 0; i < 3; i++)
        #pragma unroll
        for (int q = 0; q < 4; q++) acc[i][q] = 0.f;

    // load indices: f in {tid, tid+192}; r = f>>3 (two fixed rows/thread)
    const int r0 = tid >> 3;          // 0..23
    const int r1 = r0 + 24;           // 24..47
    const int c0 = (tid & 7) << 2;    // pixel within tile, multiple of 4
    float nq0 = 0.f, nq1 = 0.f, nk0 = 0.f, nk1 = 0.f;

    const int nbase = split * GCHUNK;

    for (int t = 0; t < GCHUNK; t += GTP) {
        // --- load 48 x 32 q and k, convert to tf32 hi/lo ---
        {
            long off0 = (long)r0*HWsz + nbase + t + c0;
            long off1 = (long)r1*HWsz + nbase + t + c0;
            float4 v0 = *(const float4*)(qp + off0);
            float4 u0 = *(const float4*)(kp + off0);
            float4 v1 = *(const float4*)(qp + off1);
            float4 u1 = *(const float4*)(kp + off1);
            #pragma unroll
            for (int j = 0; j < 4; j++) {
                float qv = (&v0.x)[j], kv = (&u0.x)[j];
                unsigned qh = f2tf32(qv), kh = f2tf32(kv);
                Qh[r0][c0+j] = qh; Ql[r0][c0+j] = f2tf32(qv - __uint_as_float(qh));
                Kh[r0][c0+j] = kh; Kl[r0][c0+j] = f2tf32(kv - __uint_as_float(kh));
                nq0 = fmaf(qv, qv, nq0);
                nk0 = fmaf(kv, kv, nk0);
            }
            #pragma unroll
            for (int j = 0; j < 4; j++) {
                float qv = (&v1.x)[j], kv = (&u1.x)[j];
                unsigned qh = f2tf32(qv), kh = f2tf32(kv);
                Qh[r1][c0+j] = qh; Ql[r1][c0+j] = f2tf32(qv - __uint_as_float(qh));
                Kh[r1][c0+j] = kh; Kl[r1][c0+j] = f2tf32(kv - __uint_as_float(kh));
                nq1 = fmaf(qv, qv, nq1);
                nk1 = fmaf(kv, kv, nk1);
            }
        }
        __syncthreads();

        #pragma unroll
        for (int ks = 0; ks < GTP; ks += 8) {
            unsigned bh0 = Kh[nb + gid][ks + tig    ];
            unsigned bh1 = Kh[nb + gid][ks + tig + 4];
            unsigned bl0 = Kl[nb + gid][ks + tig    ];
            unsigned bl1 = Kl[nb + gid][ks + tig + 4];
            #pragma unroll
            for (int mi = 0; mi < 3; mi++) {
                int mr = mi*16;
                unsigned ah[4], al[4];
                ah[0] = Qh[mr + gid    ][ks + tig    ];
                ah[1] = Qh[mr + gid + 8][ks + tig    ];
                ah[2] = Qh[mr + gid    ][ks + tig + 4];
                ah[3] = Qh[mr + gid + 8][ks + tig + 4];
                al[0] = Ql[mr + gid    ][ks + tig    ];
                al[1] = Ql[mr + gid + 8][ks + tig    ];
                al[2] = Ql[mr + gid    ][ks + tig + 4];
                al[3] = Ql[mr + gid + 8][ks + tig + 4];
                mma_tf32(acc[mi], ah, bh0, bh1);
                mma_tf32(acc[mi], ah, bl0, bl1);
                mma_tf32(acc[mi], al, bh0, bh1);
            }
        }
        __syncthreads();
    }

    // norms: one global atomic per (thread, row)
    atomicAdd(&norms[b*2*Cc + h*Dh + r0], nq0);
    atomicAdd(&norms[b*2*Cc + h*Dh + r1], nq1);
    atomicAdd(&norms[b*2*Cc + Cc + h*Dh + r0], nk0);
    atomicAdd(&norms[b*2*Cc + Cc + h*Dh + r1], nk1);

    // write output tiles
    float* gp = gram + (long)bh * Dh * Dh;
    #pragma unroll
    for (int mi = 0; mi < 3; mi++) {
        int mr = mi*16;
        int col = nb + tig*2;
        atomicAdd(&gp[(mr + gid    )*Dh + col    ], acc[mi][0]);
        atomicAdd(&gp[(mr + gid    )*Dh + col + 1], acc[mi][1]);
        atomicAdd(&gp[(mr + gid + 8)*Dh + col    ], acc[mi][2]);
        atomicAdd(&gp[(mr + gid + 8)*Dh + col + 1], acc[mi][3]);
    }
}

// ---------------- normalize + temperature + softmax (in place) --------
__global__ void attn_softmax_kernel(const float* __restrict__ temp,
                                    const float* __restrict__ norms,
                                    float* __restrict__ gram)
{
    int idx = blockIdx.x * blockDim.x + threadIdx.x;
    if (idx >= Bq*NHEADS*Dh) return;
    int d  = idx % Dh;
    int bh = idx / Dh;
    int h = bh % NHEADS, b = bh / NHEADS;

    float nq = fmaxf(sqrtf(norms[b*2*Cc + h*Dh + d]), 1e-12f);
    float t = temp[h];
    float* row = gram + (long)bh*Dh*Dh + d*Dh;

    float vals[Dh];
    float mx = -1e30f;
    #pragma unroll
    for (int e = 0; e < Dh; e++) {
        float nk = fmaxf(sqrtf(norms[b*2*Cc + Cc + h*Dh + e]), 1e-12f);
        float v = row[e] / (nq * nk) * t;
        vals[e] = v;
        mx = fmaxf(mx, v);
    }
    float s = 0.f;
    #pragma unroll
    for (int e = 0; e < Dh; e++) { vals[e] = expf(vals[e] - mx); s += vals[e]; }
    float inv = 1.f / s;
    #pragma unroll
    for (int e = 0; e < Dh; e++) row[e] = vals[e] * inv;
}

// ---------------- fold proj into attn ----------------
__global__ void fold_kernel(const float* __restrict__ proj_w,
                            const float* __restrict__ gram,
                            float* __restrict__ Mout)
{
    int idx = blockIdx.x * 256 + threadIdx.x;
    if (idx >= Bq*Cc*Cc) return;
    int he = idx % Cc;
    int o  = (idx / Cc) % Cc;
    int b  = idx / (Cc*Cc);
    int h = he / Dh, e = he % Dh;
    const float* attn = gram + ((long)(b*NHEADS + h)) * Dh * Dh;
    const float* pw = proj_w + (long)o*Cc + h*Dh;
    float s = 0.f;
    #pragma unroll
    for (int dl = 0; dl < Dh; dl++)
        s = fmaf(pw[dl], attn[dl*Dh + e], s);
    Mout[idx] = s;
}

// ---------------- launch ----------------
extern "C" void kernel_launch(void* const* d_in, const int* in_sizes, int n_in,
                              void* d_out, int out_size)
{
    const float* x      = (const float*)d_in[0];
    const float* qkv_w  = (const float*)d_in[1];
    const float* qkv_b  = (const float*)d_in[2];
    const float* dw_w   = (const float*)d_in[3];
    const float* dw_b   = (const float*)d_in[4];
    const float* temp   = (const float*)d_in[5];
    const float* proj_w = (const float*)d_in[6];
    const float* proj_b = (const float*)d_in[7];
    float* out = (float*)d_out;

    float *p_qkv, *p_qkvdw, *p_norms, *p_gram, *p_M;
    cudaGetSymbolAddress((void**)&p_qkv,   g_qkv);
    cudaGetSymbolAddress((void**)&p_qkvdw, g_qkvdw);
    cudaGetSymbolAddress((void**)&p_norms, g_norms);
    cudaGetSymbolAddress((void**)&p_gram,  g_gram);
    cudaGetSymbolAddress((void**)&p_M,     g_M);

    zero_kernel<<<(Bq*NHEADS*Dh*Dh + 255)/256, 256>>>(
        p_norms, Bq*2*Cc, p_gram, Bq*NHEADS*Dh*Dh);

    // GEMM1: qkv = qkv_w @ x (per batch)
    {
        dim3 grid(HWsz/GBN, (C3 + GBM - 1)/GBM, Bq);
        tf32_gemm_bias_kernel<<<grid, 256>>>(
            qkv_w, 0L,
            x, (long)Cc*HWsz,
            p_qkv, (long)C3*HWsz,
            qkv_b, C3, HWsz, Cc);
    }

    // depthwise 3x3
    {
        dim3 grid(Bq*C3, HWsz/1024);
        dwconv_kernel<<<grid, 256>>>(p_qkv, dw_w, dw_b, p_qkvdw);
    }

    // gram + norms
    {
        dim3 grid(Bq*NHEADS, GSPLIT);
        gram_mma_kernel<<<grid, 192>>>(p_qkvdw, p_gram, p_norms);
    }

    attn_softmax_kernel<<<(Bq*NHEADS*Dh + 255)/256, 256>>>(temp, p_norms, p_gram);

    fold_kernel<<<(Bq*Cc*Cc + 255)/256, 256>>>(proj_w, p_gram, p_M);

    // GEMM4: out = M[b] @ v + proj_b
    {
        dim3 grid(HWsz/GBN, (Cc + GBM - 1)/GBM, Bq);
        tf32_gemm_bias_kernel<<<grid, 256>>>(
            p_M, (long)Cc*Cc,
            p_qkvdw + (long)2*Cc*HWsz, (long)C3*HWsz,
            out, (long)Cc*HWsz,
            proj_b, Cc, HWsz, Cc);
    }
}